// round 9
// baseline (speedup 1.0000x reference)
#include <cuda_runtime.h>
#include <cuda_bf16.h>

#define TSTEPS  400
#define POS_INF __int_as_float(0x7f800000)
#define WSTART  240            // E window = steps [240, 384): 4 lanes x 36 steps
#define HI0     26.6f          // safe upper bound on E_239 (true bound 26.5)

// Exact reference simulation for rare rows. Matches the JAX reference op-for-op.
__device__ __noinline__ float sm2_slow_row(const float* __restrict__ row) {
    float I = 1.0f, n = 0.0f, EF = 2.5f;
    for (int t = 0; t < TSTEPS; ++t) {
        float p = row[t];
        float q = p * 5.0f;
        bool correct = (q >= 3.0f);
        bool brk = (p == -1.0f);
        float In;
        if (n >= 2.0f)      In = I * EF;
        else if (n == 1.0f) In = 6.0f;
        else                In = 1.0f;
        if (!correct) In = 1.0f;
        if (!brk) I = In;
        I = fminf(fmaxf(I, 1.0f), 274.0f);
        float d = 5.0f - q;
        EF = EF + (0.1f - d * (0.08f + d * 0.02f));
        EF = fmaxf(EF, 1.3f);
        if (correct) n += 1.0f;
    }
    return I;
}

// delta(p) = 0.1 - d*(0.08 + 0.02 d),  d = 5 - 5p
__device__ __forceinline__ float delta_of(float pv) {
    float d  = fmaf(pv, -5.0f, 5.0f);
    float t2 = fmaf(d, 0.02f, 0.08f);
    return fmaf(-d, t2, 0.1f);
}

__global__ void __launch_bounds__(256)
sm2_kernel(const float* __restrict__ p, float* __restrict__ out, int B) {
    const unsigned FULL = 0xFFFFFFFFu;
    int gwarp = (blockIdx.x * blockDim.x + threadIdx.x) >> 5;
    int lane  = threadIdx.x & 31;
    int q     = lane & 3;                      // position within 4-lane row group

    int row0 = gwarp * 8 + (lane >> 2);        // 8 rows per warp
    int row  = (row0 < B) ? row0 : (B - 1);    // clamp: full warp active for shfl
    const float* rp = p + (size_t)row * TSTEPS;

    // ---- loads (all hoisted; 13 LDG.128 in flight per lane) ----
    // window: lane q owns CONTIGUOUS steps [240+36q, 240+36q+36); 144B, 16B-aligned
    const float* wp = rp + WSTART + q * 36;
    float4 wb[9];
    #pragma unroll
    for (int j = 0; j < 9; ++j)
        wb[j] = *reinterpret_cast<const float4*>(wp + j * 4);
    // tail: steps [384,400), broadcast to all 4 lanes of the group
    float4 tb[4];
    #pragma unroll
    for (int j = 0; j < 4; ++j)
        tb[j] = *reinterpret_cast<const float4*>(rp + 384 + j * 4);

    // ---- window: prefix-sum + running-min fold, plus correctness count ----
    // m_n = 1.3 + P_n - min_k P_k  (max-plus with floor, prefix-min form)
    float s = 0.0f, mn = POS_INF;
    int   c = 0;                 // corrects on even-index steps (guard only; >=2 needed)
    #pragma unroll
    for (int j = 0; j < 9; ++j) {
        float pv[4] = {wb[j].x, wb[j].y, wb[j].z, wb[j].w};
        #pragma unroll
        for (int k = 0; k < 4; ++k) {
            s += delta_of(pv[k]);
            mn = fminf(mn, s);
            if ((k & 1) == 0)
                c += (pv[k] >= 0.6f);   // UNDERcounts vs q>=3 -> conservative
        }
    }
    float m = 1.3f + (s - mn);   // per-lane 36-step composition (s, m)

    // Ordered 2-level tree reduce across the 4 lanes (leader q==0 gets all 144).
    #pragma unroll
    for (int off = 1; off <= 2; off <<= 1) {
        float so = __shfl_down_sync(FULL, s, off, 4);
        float mo = __shfl_down_sync(FULL, m, off, 4);
        int   co = __shfl_down_sync(FULL, c, off, 4);
        m = fmaxf(m + so, mo);   // self earlier in time, other later
        s = s + so;
        c = c + co;
    }
    // Leader: collapse test (floor reset erases history) + correct-count guard.
    int ok = (m >= HI0 + s) && (c >= 2);
    float Mg  = __shfl_sync(FULL, m, 0, 4);    // E_383 when collapsed
    int   okg = __shfl_sync(FULL, ok, 0, 4);

    // ---- tail t = 384..399: direct I simulation (exact when a tail step is
    // incorrect; the all-correct case routes to the slow path) ----
    float E = Mg;                // E_{t-1} entering step t
    float I = 1.0f;              // exact: any pre-384 run is erased by first incorrect
    int allc = 1;
    #pragma unroll
    for (int j = 0; j < 4; ++j) {
        float pv[4] = {tb[j].x, tb[j].y, tb[j].z, tb[j].w};
        #pragma unroll
        for (int k = 0; k < 4; ++k) {
            bool corr = (pv[k] * 5.0f >= 3.0f);      // exact reference predicate
            I = corr ? fminf(I * E, 274.0f) : 1.0f;  // uses EF_{t-1}; progressive clip
            allc &= (int)corr;
            E = fmaxf(E + delta_of(pv[k]), 1.3f);
        }
    }

    if (!(okg && !allc))
        I = sm2_slow_row(rp);    // ~1e-5/row; exact resimulation

    if (q == 0 && row0 < B)
        out[row] = fminf(2.0f * I, 274.0f);
}

extern "C" void kernel_launch(void* const* d_in, const int* in_sizes, int n_in,
                              void* d_out, int out_size) {
    const float* p = (const float*)d_in[0];
    float* out = (float*)d_out;
    int B = out_size;
    int rowsPerBlock = 64;               // 256 threads = 8 warps * 8 rows
    int blocks = (B + rowsPerBlock - 1) / rowsPerBlock;
    sm2_kernel<<<blocks, 256>>>(p, out, B);
}